// round 4
// baseline (speedup 1.0000x reference)
#include <cuda_runtime.h>
#include <cuda_bf16.h>
#include <math.h>
#include <float.h>

// Gate_33827162423867: fused router
//   score = x[tokens,dim] @ W[64,dim]^T (split-K=4 accumulation, emulating
//   cublasLt splitK: serial fp32 fma within each K/4 slice, partials folded
//   serially) -> softmax (FTZ semantics, matching XLA:GPU) -> top-8 of the
//   softmax probabilities (ties, incl. flushed zeros, break to lowest index).
// Output layout: d_out float*, [0, tokens*8) = gate weights,
// [tokens*8, 2*tokens*8) = indices (as float).

constexpr int TB = 128;   // tokens per CTA
constexpr int NE = 64;    // experts
constexpr int KC = 32;    // K chunk
constexpr int NT = 256;   // threads per CTA
constexpr int TOPK = 8;
constexpr int SPLITK = 4; // K slices (accumulation-order emulation)

__global__ __launch_bounds__(NT, 1)
void gate_fused_kernel(const float* __restrict__ x,
                       const float* __restrict__ w,
                       float* __restrict__ out,
                       int dim, int tokens)
{
    // sbuf reused: phase 1: xs[KC][TB] (4096 f) + ws[KC][NE] (2048 f)
    //              phase 2: scores[TB][NE] (8192 f)
    __shared__ float sbuf[8192];
    float* xs = sbuf;            // [KC][TB] transposed x chunk
    float* ws = sbuf + KC * TB;  // [KC][NE]

    const int tid = threadIdx.x;
    const int tg  = tid & 31;    // token group: tokens tg*4 .. tg*4+3
    const int eg  = tid >> 5;    // expert group: experts eg*8 .. eg*8+7
    const int token0 = blockIdx.x * TB;

    const int slice_len = dim / SPLITK;   // 1024

    float tot[4][8];   // running serial combine of slice partials
    float acc[4][8];   // current slice partial
    #pragma unroll
    for (int t = 0; t < 4; t++)
        #pragma unroll
        for (int e = 0; e < 8; e++) { tot[t][e] = 0.0f; acc[t][e] = 0.0f; }

    for (int k0 = 0; k0 < dim; k0 += KC) {
        // ---- load x chunk: TB rows x KC cols -> xs[k][t] (transposed) ----
        #pragma unroll
        for (int i = 0; i < 4; i++) {
            int idx = tid + i * NT;            // 0..1023
            int t   = idx & (TB - 1);
            int kk  = (idx >> 7) * 4;
            float4 v = *reinterpret_cast<const float4*>(
                &x[(size_t)(token0 + t) * dim + k0 + kk]);
            xs[(kk + 0) * TB + t] = v.x;
            xs[(kk + 1) * TB + t] = v.y;
            xs[(kk + 2) * TB + t] = v.z;
            xs[(kk + 3) * TB + t] = v.w;
        }
        // ---- load w chunk: NE rows x KC cols -> ws[k][e] ----
        #pragma unroll
        for (int i = 0; i < 2; i++) {
            int idx = tid + i * NT;            // 0..511
            int e   = idx & (NE - 1);
            int kk  = (idx >> 6) * 4;
            float4 v = *reinterpret_cast<const float4*>(
                &w[(size_t)e * dim + k0 + kk]);
            ws[(kk + 0) * NE + e] = v.x;
            ws[(kk + 1) * NE + e] = v.y;
            ws[(kk + 2) * NE + e] = v.z;
            ws[(kk + 3) * NE + e] = v.w;
        }
        __syncthreads();

        // ---- compute: acc[t][e] += xs[k][tg*4+t] * ws[k][eg*8+e] ----
        #pragma unroll
        for (int k = 0; k < KC; k++) {
            float4 xa = *reinterpret_cast<const float4*>(&xs[k * TB + tg * 4]);
            float4 wa = *reinterpret_cast<const float4*>(&ws[k * NE + eg * 8]);
            float4 wb = *reinterpret_cast<const float4*>(&ws[k * NE + eg * 8 + 4]);
            float xv[4] = {xa.x, xa.y, xa.z, xa.w};
            float wv[8] = {wa.x, wa.y, wa.z, wa.w, wb.x, wb.y, wb.z, wb.w};
            #pragma unroll
            for (int t = 0; t < 4; t++)
                #pragma unroll
                for (int e = 0; e < 8; e++)
                    acc[t][e] = fmaf(xv[t], wv[e], acc[t][e]);
        }
        __syncthreads();

        // ---- slice boundary: fold partial into running total (serial) ----
        if (((k0 + KC) % slice_len) == 0) {
            #pragma unroll
            for (int t = 0; t < 4; t++)
                #pragma unroll
                for (int e = 0; e < 8; e++) {
                    tot[t][e] += acc[t][e];
                    acc[t][e] = 0.0f;
                }
        }
    }

    // ---- stash scores: sbuf[t][e] ----
    #pragma unroll
    for (int t = 0; t < 4; t++)
        #pragma unroll
        for (int e = 0; e < 8; e++)
            sbuf[(size_t)(tg * 4 + t) * NE + eg * 8 + e] = tot[t][e];
    __syncthreads();

    // ---- softmax (FTZ) + top-8 on probabilities : one thread per token ----
    if (tid < TB) {
        float* s = &sbuf[(size_t)tid * NE];
        float m = -FLT_MAX;
        #pragma unroll
        for (int e = 0; e < NE; e++) m = fmaxf(m, s[e]);

        float denom = 0.0f;
        float p[NE];
        #pragma unroll
        for (int e = 0; e < NE; e++) {
            float q = expf(s[e] - m);
            if (q < FLT_MIN) q = 0.0f;        // emulate XLA:GPU ftz on exp
            p[e] = q;
            denom += q;
        }
        float inv = 1.0f / denom;
        #pragma unroll
        for (int e = 0; e < NE; e++) {
            float q = p[e] * inv;
            if (q < FLT_MIN) q = 0.0f;        // ftz after normalization
            p[e] = q;
        }

        const int tglob = token0 + tid;
        float* out_w   = out + (size_t)tglob * TOPK;
        float* out_idx = out + (size_t)tokens * TOPK + (size_t)tglob * TOPK;

        #pragma unroll
        for (int j = 0; j < TOPK; j++) {
            float best = -1.0f;   // probs are >= 0
            int   bi   = 0;
            // strict '>' keeps lowest index on ties (incl. flushed zeros),
            // matching jax.lax.top_k on the softmax output
            for (int e = 0; e < NE; e++) {
                if (p[e] > best) { best = p[e]; bi = e; }
            }
            p[bi] = -1.0f;
            out_w[j]   = best;
            out_idx[j] = (float)bi;
        }
    }
}

extern "C" void kernel_launch(void* const* d_in, const int* in_sizes, int n_in,
                              void* d_out, int out_size)
{
    const float* x = (const float*)d_in[0];
    const float* w = (const float*)d_in[1];
    // d_in[2] = bias: dead code in the reference (softmax path, no bias add)

    const int num_experts = in_sizes[2];               // 64
    const int dim         = in_sizes[1] / num_experts; // 4096
    const int tokens      = in_sizes[0] / dim;         // 16384

    float* out = (float*)d_out;

    dim3 grid(tokens / TB);
    dim3 block(NT);
    gate_fused_kernel<<<grid, block>>>(x, w, out, dim, tokens);
}

// round 7
// speedup vs baseline: 1.0176x; 1.0176x over previous
#include <cuda_runtime.h>
#include <cuda_bf16.h>
#include <math.h>
#include <float.h>
#include <stdint.h>

// Gate_33827162423867 — tensor-core (HMMA mma.sync) router.
// score = x[16384,4096] @ W[64,4096]^T via bf16 2-split (hi/lo, 3 products,
// fp32 accum) -> FTZ softmax -> top-8 of probs. Knife-edge tokens (tiny
// top-9 logit gaps or logits near FTZ flush boundaries) are recomputed
// exactly (serial fp32 FMA, split-K4 folding == cublas splitK order) by a
// fixup kernel that overwrites their output rows.
// NOTE: toolchain targets base sm_100 (no 'a' features) => no tcgen05;
// mma.sync.m16n8k16.bf16 + ldmatrix only.
// Output: d_out float*, [0,T*8) gate weights, [T*8, 2*T*8) indices-as-float.

#define NE    64
#define TB    128
#define KCH   64
#define NT    256
#define TOPK  8

#define EPS_GAP 0.01f
#define EPS_B   0.01f
#define LN_FLT_MIN -87.33654475055310898657124730373f

// row stride in bf16 elements for smem tiles (64 data + 8 pad; 144B rows:
// 16B-aligned and bank-phase-shifted for conflict-free ldmatrix)
#define RS 72

// ---------------- device scratch (no allocs allowed) ----------------
__device__ int g_flag_count;
__device__ int g_flag_list[16384];

// ---------------- helpers ----------------
__device__ __forceinline__ uint32_t smem_u32(const void* p) {
    uint32_t a;
    asm("{ .reg .u64 t; cvta.to.shared.u64 t, %1; cvt.u32.u64 %0, t; }"
        : "=r"(a) : "l"(p));
    return a;
}
// pack two f32 -> bf16x2 (arg lo -> low half, arg hi -> high half), RN
__device__ __forceinline__ uint32_t cvt_bf16x2(float lo, float hi) {
    uint32_t r;
    asm("cvt.rn.bf16x2.f32 %0, %1, %2;" : "=r"(r) : "f"(hi), "f"(lo));
    return r;
}
__device__ __forceinline__ float bflo_f(uint32_t h) { return __uint_as_float(h << 16); }
__device__ __forceinline__ float bfhi_f(uint32_t h) { return __uint_as_float(h & 0xFFFF0000u); }

__device__ __forceinline__ void ldm_x4(uint32_t addr, uint32_t& r0, uint32_t& r1,
                                       uint32_t& r2, uint32_t& r3) {
    asm volatile("ldmatrix.sync.aligned.m8n8.x4.shared.b16 {%0,%1,%2,%3}, [%4];"
                 : "=r"(r0), "=r"(r1), "=r"(r2), "=r"(r3) : "r"(addr));
}
__device__ __forceinline__ void mma_bf16(float* d, uint32_t a0, uint32_t a1,
                                         uint32_t a2, uint32_t a3,
                                         uint32_t b0, uint32_t b1) {
    asm volatile(
        "mma.sync.aligned.m16n8k16.row.col.f32.bf16.bf16.f32 "
        "{%0,%1,%2,%3}, {%4,%5,%6,%7}, {%8,%9}, {%0,%1,%2,%3};"
        : "+f"(d[0]), "+f"(d[1]), "+f"(d[2]), "+f"(d[3])
        : "r"(a0), "r"(a1), "r"(a2), "r"(a3), "r"(b0), "r"(b1));
}

// ---------------- dynamic smem layout (bytes) ----------------
// xh: 128 x RS bf16 = 18432 ; xl: 18432 ; wh: 64 x RS = 9216 ; wl: 9216
#define SM_XH 0
#define SM_XL 18432
#define SM_WH 36864
#define SM_WL 46080
#define SMEM_DYN 55296

// ================= softmax/FTZ/top-8 epilogue (shared logic) =================
__device__ __forceinline__ void epilogue_token(const float* s, int tglob, int tokens,
                                               float* out, bool do_flag) {
    float m = -FLT_MAX;
    #pragma unroll
    for (int e = 0; e < NE; e++) m = fmaxf(m, s[e]);

    float denom = 0.0f;
    float p[NE];
    #pragma unroll
    for (int e = 0; e < NE; e++) {
        float q = expf(s[e] - m);
        if (q < FLT_MIN) q = 0.0f;           // XLA ftz on exp
        p[e] = q;
        denom += q;
    }
    float inv = 1.0f / denom;
    #pragma unroll
    for (int e = 0; e < NE; e++) {
        float q = p[e] * inv;
        if (q < FLT_MIN) q = 0.0f;           // ftz after normalization
        p[e] = q;
    }

    if (do_flag) {
        bool flag = false;
        float b2 = LN_FLT_MIN + logf(denom);
        for (int e = 0; e < NE; e++) {
            float d = s[e] - m;
            if (fabsf(d - LN_FLT_MIN) < EPS_B || fabsf(d - b2) < EPS_B) flag = true;
        }
        unsigned long long used = 0ull;
        float prevv = 0.0f;
        for (int j = 0; j < 9; j++) {
            float best = -FLT_MAX; int bi = 0;
            for (int e = 0; e < NE; e++)
                if (!((used >> e) & 1ull) && s[e] > best) { best = s[e]; bi = e; }
            used |= 1ull << bi;
            if (j > 0 && (prevv - best) < EPS_GAP) flag = true;
            prevv = best;
        }
        if (flag) {
            int i = atomicAdd(&g_flag_count, 1);
            if (i < 16384) g_flag_list[i] = tglob;
        }
    }

    float* out_w   = out + (size_t)tglob * TOPK;
    float* out_idx = out + (size_t)tokens * TOPK + (size_t)tglob * TOPK;
    #pragma unroll
    for (int j = 0; j < TOPK; j++) {
        float best = -1.0f; int bi = 0;
        for (int e = 0; e < NE; e++)
            if (p[e] > best) { best = p[e]; bi = e; }   // '>' : lowest idx wins ties
        p[bi] = -1.0f;
        out_w[j]   = best;
        out_idx[j] = (float)bi;
    }
}

// ================= kernel 0: reset flag counter =================
__global__ void reset_kernel() {
    if (threadIdx.x == 0) g_flag_count = 0;
}

// ================= kernel 1: HMMA GEMM + epilogue =================
__global__ __launch_bounds__(NT, 1)
void gate_mma_kernel(const float* __restrict__ x,
                     const float* __restrict__ w,
                     float* __restrict__ out,
                     int dim, int tokens)
{
    extern __shared__ char dyn[];
    const uint32_t sbase = smem_u32(dyn);

    const int tid  = threadIdx.x;
    const int wid  = tid >> 5;
    const int lane = tid & 31;
    const int token0 = blockIdx.x * TB;

    // convert mappings
    const int xrow  = tid >> 1;           // 0..127
    const int xcol0 = (tid & 1) * 32;     // 0 or 32
    const int wrow  = tid >> 2;           // 0..63
    const int wcol0 = (tid & 3) * 16;     // 0,16,32,48

    // ldmatrix per-lane offsets (bytes), constant across chunks
    // A (x): m0=(r0-7,kLo) m1=(r8-15,kLo) m2=(r0-7,kHi) m3=(r8-15,kHi)
    const int tokb = wid * 16;
    const uint32_t aoff = (uint32_t)((tokb + (lane & 7) + (((lane >> 3) & 1) * 8)) * (RS * 2)
                                     + ((lane >> 4) * 16));
    // B (w): m0=(e0-7,kLo) m1=(e0-7,kHi) m2=(e8-15,kLo) m3=(e8-15,kHi)
    const uint32_t boff_base = (uint32_t)(((lane & 7) + ((lane >> 4) * 8)) * (RS * 2)
                                          + (((lane >> 3) & 1) * 16));

    float acc[8][4];
    #pragma unroll
    for (int n = 0; n < 8; n++)
        #pragma unroll
        for (int i = 0; i < 4; i++) acc[n][i] = 0.0f;

    const int nchunks = dim / KCH;        // 64

    // register preload buffers
    float4 xr[8];
    float4 wr[4];
    {
        const float* xsrc = x + (size_t)(token0 + xrow) * dim + xcol0;
        #pragma unroll
        for (int i = 0; i < 4; i++) {
            xr[2 * i]     = *reinterpret_cast<const float4*>(xsrc + i * 8);
            xr[2 * i + 1] = *reinterpret_cast<const float4*>(xsrc + i * 8 + 4);
        }
        const float* wsrc = w + (size_t)wrow * dim + wcol0;
        #pragma unroll
        for (int i = 0; i < 2; i++) {
            wr[2 * i]     = *reinterpret_cast<const float4*>(wsrc + i * 8);
            wr[2 * i + 1] = *reinterpret_cast<const float4*>(wsrc + i * 8 + 4);
        }
    }

    for (int c = 0; c < nchunks; c++) {
        if (c > 0) __syncthreads();   // prev MMA phase done before overwrite

        // ---- convert + store current chunk ----
        {
            char* xh = dyn + SM_XH;
            char* xl = dyn + SM_XL;
            #pragma unroll
            for (int i = 0; i < 4; i++) {
                float4 a = xr[2 * i], b = xr[2 * i + 1];
                uint32_t h0 = cvt_bf16x2(a.x, a.y);
                uint32_t h1 = cvt_bf16x2(a.z, a.w);
                uint32_t h2 = cvt_bf16x2(b.x, b.y);
                uint32_t h3 = cvt_bf16x2(b.z, b.w);
                uint32_t l0 = cvt_bf16x2(a.x - bflo_f(h0), a.y - bfhi_f(h0));
                uint32_t l1 = cvt_bf16x2(a.z - bflo_f(h1), a.w - bfhi_f(h1));
                uint32_t l2 = cvt_bf16x2(b.x - bflo_f(h2), b.y - bfhi_f(h2));
                uint32_t l3 = cvt_bf16x2(b.z - bflo_f(h3), b.w - bfhi_f(h3));
                uint32_t off = (uint32_t)(xrow * (RS * 2) + (xcol0 + i * 8) * 2);
                *reinterpret_cast<uint4*>(xh + off) = make_uint4(h0, h1, h2, h3);
                *reinterpret_cast<uint4*>(xl + off) = make_uint4(l0, l1, l2, l3);
            }
            char* wh = dyn + SM_WH;
            char* wl = dyn + SM_WL;
            #pragma unroll
            for (int i = 0; i < 2; i++) {
                float4 a = wr[2 * i], b = wr[2 * i + 1];
                uint32_t h0 = cvt_bf16x2(a.x, a.y);
                uint32_t h1 = cvt_bf16x2(a.z, a.w);
                uint32_t h2 = cvt_bf16x2(b.x, b.y);
                uint32_t h3 = cvt_bf16x2(b.z, b.w);
                uint32_t l0 = cvt_bf16x2(a.x - bflo_f(h0), a.y - bfhi_f(h0));
                uint32_t l1 = cvt_bf16x2(a.z - bflo_f(h1), a.w - bfhi_f(h1));
                uint32_t l2 = cvt_bf16x2(b.x - bflo_f(h2), b.y - bfhi_f(h2));
                uint32_t l3 = cvt_bf16x2(b.z - bflo_f(h3), b.w - bfhi_f(h3));
                uint32_t off = (uint32_t)(wrow * (RS * 2) + (wcol0 + i * 8) * 2);
                *reinterpret_cast<uint4*>(wh + off) = make_uint4(h0, h1, h2, h3);
                *reinterpret_cast<uint4*>(wl + off) = make_uint4(l0, l1, l2, l3);
            }
        }

        // ---- preload next chunk (hides behind MMA phase) ----
        if (c + 1 < nchunks) {
            const int k0n = (c + 1) * KCH;
            const float* xsrc = x + (size_t)(token0 + xrow) * dim + k0n + xcol0;
            #pragma unroll
            for (int i = 0; i < 4; i++) {
                xr[2 * i]     = *reinterpret_cast<const float4*>(xsrc + i * 8);
                xr[2 * i + 1] = *reinterpret_cast<const float4*>(xsrc + i * 8 + 4);
            }
            const float* wsrc = w + (size_t)wrow * dim + k0n + wcol0;
            #pragma unroll
            for (int i = 0; i < 2; i++) {
                wr[2 * i]     = *reinterpret_cast<const float4*>(wsrc + i * 8);
                wr[2 * i + 1] = *reinterpret_cast<const float4*>(wsrc + i * 8 + 4);
            }
        }
        __syncthreads();

        // ---- MMA phase: 4 k-steps x 8 n-tiles x 3 products ----
        #pragma unroll
        for (int ks = 0; ks < 4; ks++) {
            const uint32_t kb = (uint32_t)(ks * 32);
            uint32_t ah0, ah1, ah2, ah3, al0, al1, al2, al3;
            ldm_x4(sbase + SM_XH + aoff + kb, ah0, ah1, ah2, ah3);
            ldm_x4(sbase + SM_XL + aoff + kb, al0, al1, al2, al3);
            #pragma unroll
            for (int p = 0; p < 4; p++) {
                const uint32_t bo = boff_base + (uint32_t)(p * 16 * (RS * 2)) + kb;
                uint32_t bh0, bh1, bh2, bh3, bl0, bl1, bl2, bl3;
                ldm_x4(sbase + SM_WH + bo, bh0, bh1, bh2, bh3);
                ldm_x4(sbase + SM_WL + bo, bl0, bl1, bl2, bl3);
                // n-tile 2p (experts p*16..p*16+7)
                mma_bf16(acc[2 * p], ah0, ah1, ah2, ah3, bh0, bh1);
                mma_bf16(acc[2 * p], ah0, ah1, ah2, ah3, bl0, bl1);
                mma_bf16(acc[2 * p], al0, al1, al2, al3, bh0, bh1);
                // n-tile 2p+1 (experts p*16+8..p*16+15)
                mma_bf16(acc[2 * p + 1], ah0, ah1, ah2, ah3, bh2, bh3);
                mma_bf16(acc[2 * p + 1], ah0, ah1, ah2, ah3, bl2, bl3);
                mma_bf16(acc[2 * p + 1], al0, al1, al2, al3, bh2, bh3);
            }
        }
    }

    __syncthreads();

    // ---- write accumulators to smem scores [128][64] ----
    float* scores = reinterpret_cast<float*>(dyn);
    {
        const int g = lane >> 2;          // 0..7
        const int t2 = (lane & 3) * 2;    // 0,2,4,6
        #pragma unroll
        for (int n = 0; n < 8; n++) {
            const int col = n * 8 + t2;
            scores[(tokb + g) * NE + col]         = acc[n][0];
            scores[(tokb + g) * NE + col + 1]     = acc[n][1];
            scores[(tokb + g + 8) * NE + col]     = acc[n][2];
            scores[(tokb + g + 8) * NE + col + 1] = acc[n][3];
        }
    }
    __syncthreads();

    if (tid < TB)
        epilogue_token(&scores[(size_t)tid * NE], token0 + tid, tokens, out, true);
}

// ================= kernel 2: exact fixup for flagged tokens =================
#define FG 8
__global__ __launch_bounds__(128, 1)
void fixup_kernel(const float* __restrict__ x,
                  const float* __restrict__ w,
                  float* __restrict__ out,
                  int dim, int tokens)
{
    __shared__ float ws[KCH * NE];     // [k][e]  16KB
    __shared__ float xs[FG * KCH];     // [j][k]  2KB
    __shared__ float sc[FG * NE];      // [j][e]  2KB
    __shared__ int   toks[FG];

    const int tid = threadIdx.x;
    const int e     = tid & 63;
    const int jbase = tid >> 6;        // 0..1 ; chains j = jbase + 2*{0..3}
    const int count = g_flag_count < 16384 ? g_flag_count : 16384;

    for (int g0 = blockIdx.x * FG; g0 < count; g0 += gridDim.x * FG) {
        const int ng = min(FG, count - g0);
        __syncthreads();
        if (tid < FG)
            toks[tid] = g_flag_list[g0 + (tid < ng ? tid : 0)];
        __syncthreads();

        float acc[4] = {0, 0, 0, 0};
        float tot[4] = {0, 0, 0, 0};

        for (int kc = 0; kc < dim; kc += KCH) {
            __syncthreads();
            for (int idx = tid; idx < NE * (KCH / 4); idx += 128) {
                int row = idx >> 4;            // expert
                int c4  = (idx & 15) * 4;      // k base
                float4 v = *reinterpret_cast<const float4*>(&w[(size_t)row * dim + kc + c4]);
                ws[(c4 + 0) * NE + row] = v.x;
                ws[(c4 + 1) * NE + row] = v.y;
                ws[(c4 + 2) * NE + row] = v.z;
                ws[(c4 + 3) * NE + row] = v.w;
            }
            {
                int j  = tid >> 4;             // 0..7
                int c4 = (tid & 15) * 4;
                float4 v = *reinterpret_cast<const float4*>(&x[(size_t)toks[j] * dim + kc + c4]);
                *reinterpret_cast<float4*>(&xs[j * KCH + c4]) = v;
            }
            __syncthreads();

            for (int k = 0; k < KCH; k++) {
                float wv = ws[k * NE + e];
                #pragma unroll
                for (int j4 = 0; j4 < 4; j4++)
                    acc[j4] = fmaf(xs[(jbase + 2 * j4) * KCH + k], wv, acc[j4]);
            }
            if (((kc + KCH) & 1023) == 0) {    // split-K4 fold (every 1024)
                #pragma unroll
                for (int j4 = 0; j4 < 4; j4++) { tot[j4] += acc[j4]; acc[j4] = 0.0f; }
            }
        }
        #pragma unroll
        for (int j4 = 0; j4 < 4; j4++) {
            int j = jbase + 2 * j4;
            if (j < ng) sc[j * NE + e] = tot[j4];
        }
        __syncthreads();
        if (tid < ng)
            epilogue_token(&sc[(size_t)tid * NE], toks[tid], tokens, out, false);
    }
}

// ================= launch =================
extern "C" void kernel_launch(void* const* d_in, const int* in_sizes, int n_in,
                              void* d_out, int out_size)
{
    const float* x = (const float*)d_in[0];
    const float* w = (const float*)d_in[1];
    // d_in[2] = bias: dead code in the reference

    const int num_experts = in_sizes[2];                 // 64
    const int dim         = in_sizes[1] / num_experts;   // 4096
    const int tokens      = in_sizes[0] / dim;           // 16384
    float* out = (float*)d_out;

    // idempotent, called every time (no static guards allowed)
    cudaFuncSetAttribute(gate_mma_kernel,
                         cudaFuncAttributeMaxDynamicSharedMemorySize, SMEM_DYN);

    reset_kernel<<<1, 32>>>();
    gate_mma_kernel<<<tokens / TB, NT, SMEM_DYN>>>(x, w, out, dim, tokens);
    fixup_kernel<<<128, 128>>>(x, w, out, dim, tokens);
}